// round 5
// baseline (speedup 1.0000x reference)
#include <cuda_runtime.h>
#include <cstdint>
#include <cstddef>
#include <math.h>

#define BB 2
#define TT 2048
#define CC 1024
#define HH 16
#define NROWS (BB*TT)   // 4096

// ---------------- scratch (static device allocations; no cudaMalloc) -------
__device__ float g_qw[CC*CC];
__device__ float g_kw[CC*CC];
__device__ float g_vw[CC*CC];
__device__ float g_q[NROWS*CC];
__device__ float g_k[NROWS*CC];
__device__ float g_v[NROWS*CC];
__device__ float g_y[NROWS*CC];
__device__ float g_ga[NROWS*HH];

__device__ __forceinline__ void cp_async16(uint32_t saddr, const void* g) {
    asm volatile("cp.async.cg.shared.global [%0], [%1], 16;\n" :: "r"(saddr), "l"(g));
}
__device__ __forceinline__ void cp_commit() {
    asm volatile("cp.async.commit_group;\n");
}
__device__ __forceinline__ void cp_wait0() {
    asm volatile("cp.async.wait_group 0;\n");
}
__device__ __forceinline__ void cp_wait1() {
    asm volatile("cp.async.wait_group 1;\n");
}

// ---------------- 1) fuse mix into weights ---------------------------------
__global__ void fuse_kernel(const float* __restrict__ cq, const float* __restrict__ ck,
                            const float* __restrict__ cv, const float* __restrict__ qm,
                            const float* __restrict__ km, const float* __restrict__ vm) {
    int row = blockIdx.x;
    int wi  = blockIdx.y;
    const float* W = (wi == 0) ? cq : (wi == 1) ? ck : cv;
    const float* M = (wi == 0) ? qm : (wi == 1) ? km : vm;
    float* O       = (wi == 0) ? g_qw : (wi == 1) ? g_kw : g_vw;
    int h = row >> 6, d = row & 63;
    float mx[16];
#pragma unroll
    for (int m = 0; m < 16; m++) mx[m] = M[h*16 + m];
    for (int c = threadIdx.x; c < CC; c += blockDim.x) {
        float s = 0.f;
#pragma unroll
        for (int m = 0; m < 16; m++) s += mx[m] * W[(m*64 + d)*CC + c];
        O[row*CC + c] = s;
    }
}

// ---------------- 2) NT SGEMM, double-buffered, up to 3 problems via z ------
__global__ __launch_bounds__(256, 2) void gemm_nt_kernel(
    const float* __restrict__ A,
    const float* __restrict__ B0, float* __restrict__ C0,
    const float* __restrict__ B1, float* __restrict__ C1,
    const float* __restrict__ B2, float* __restrict__ C2,
    int K) {
    const float* Bm = (blockIdx.z == 0) ? B0 : (blockIdx.z == 1) ? B1 : B2;
    float*       Cm = (blockIdx.z == 0) ? C0 : (blockIdx.z == 1) ? C1 : C2;
    const int N = CC;

    __shared__ float As[2][8][132];
    __shared__ float Bs[2][8][132];
    const int tid = threadIdx.x;
    const int tx = tid & 15, ty = tid >> 4;
    const int brow = blockIdx.x * 128, bcol = blockIdx.y * 128;

    const int lr = tid >> 1;
    const int lc = (tid & 1) * 4;
    const float* Abase = A  + (size_t)(brow + lr) * K + lc;
    const float* Bbase = Bm + (size_t)(bcol + lr) * K + lc;

    float acc[8][8];
#pragma unroll
    for (int i = 0; i < 8; i++)
#pragma unroll
        for (int j = 0; j < 8; j++) acc[i][j] = 0.f;

    {
        float4 a = *(const float4*)Abase;
        float4 b = *(const float4*)Bbase;
        As[0][lc+0][lr] = a.x; As[0][lc+1][lr] = a.y;
        As[0][lc+2][lr] = a.z; As[0][lc+3][lr] = a.w;
        Bs[0][lc+0][lr] = b.x; Bs[0][lc+1][lr] = b.y;
        Bs[0][lc+2][lr] = b.z; Bs[0][lc+3][lr] = b.w;
    }
    __syncthreads();

    int p = 0;
    for (int kk = 0; kk < K; kk += 8) {
        const bool has = (kk + 8) < K;
        float4 an, bn;
        if (has) {
            an = *(const float4*)(Abase + kk + 8);
            bn = *(const float4*)(Bbase + kk + 8);
        }
#pragma unroll
        for (int k = 0; k < 8; k++) {
            float4 a0 = *(const float4*)&As[p][k][ty*8];
            float4 a1 = *(const float4*)&As[p][k][ty*8 + 4];
            float4 b0 = *(const float4*)&Bs[p][k][tx*8];
            float4 b1 = *(const float4*)&Bs[p][k][tx*8 + 4];
            float ar[8] = {a0.x,a0.y,a0.z,a0.w,a1.x,a1.y,a1.z,a1.w};
            float br[8] = {b0.x,b0.y,b0.z,b0.w,b1.x,b1.y,b1.z,b1.w};
#pragma unroll
            for (int i = 0; i < 8; i++)
#pragma unroll
                for (int j = 0; j < 8; j++) acc[i][j] += ar[i]*br[j];
        }
        if (has) {
            int q = p ^ 1;
            As[q][lc+0][lr] = an.x; As[q][lc+1][lr] = an.y;
            As[q][lc+2][lr] = an.z; As[q][lc+3][lr] = an.w;
            Bs[q][lc+0][lr] = bn.x; Bs[q][lc+1][lr] = bn.y;
            Bs[q][lc+2][lr] = bn.z; Bs[q][lc+3][lr] = bn.w;
            __syncthreads();
            p = q;
        }
    }
#pragma unroll
    for (int i = 0; i < 8; i++) {
        int row = brow + ty*8 + i;
        float* dst = Cm + (size_t)row * N + bcol + tx*8;
        float4 w0 = {acc[i][0], acc[i][1], acc[i][2], acc[i][3]};
        float4 w1 = {acc[i][4], acc[i][5], acc[i][6], acc[i][7]};
        *(float4*)dst = w0;
        *(float4*)(dst + 4) = w1;
    }
}

// ---------------- 3) gates + RoPE + RMSNorm (one warp per (b,t,h)) ----------
__global__ void post_kernel(const float* __restrict__ x, const float* __restrict__ ve,
                            const float* __restrict__ cosb, const float* __restrict__ sinb,
                            const float* __restrict__ vgw, const float* __restrict__ agw) {
    int gw   = (blockIdx.x * blockDim.x + threadIdx.x) >> 5;
    int lane = threadIdx.x & 31;
    if (gw >= NROWS*HH) return;
    int h  = gw % HH;
    int bt = gw / HH;
    int t  = bt % TT;
    size_t xbase = (size_t)bt * CC;

    float gv = x[xbase + lane] * vgw[h*32 + lane];
#pragma unroll
    for (int o = 16; o > 0; o >>= 1) gv += __shfl_xor_sync(0xffffffffu, gv, o);
    float gate_v = 2.f / (1.f + __expf(-gv));

    float ga = (lane < 12) ? x[xbase + lane] * agw[h*12 + lane] : 0.f;
#pragma unroll
    for (int o = 16; o > 0; o >>= 1) ga += __shfl_xor_sync(0xffffffffu, ga, o);
    if (lane == 0) g_ga[(size_t)bt*HH + h] = 1.f / (1.f + __expf(-ga));

    size_t idx = xbase + h*64;
    g_v[idx + lane]      += gate_v * ve[idx + lane];
    g_v[idx + lane + 32] += gate_v * ve[idx + lane + 32];

    float cs = cosb[t*32 + lane], sn = sinb[t*32 + lane];
    {
        float q1 = g_q[idx + lane], q2 = g_q[idx + lane + 32];
        float r1 =  q1*cs + q2*sn;
        float r2 = -q1*sn + q2*cs;
        float ss = r1*r1 + r2*r2;
#pragma unroll
        for (int o = 16; o > 0; o >>= 1) ss += __shfl_xor_sync(0xffffffffu, ss, o);
        float sc = rsqrtf(ss * (1.f/64.f) + 1e-6f);
        g_q[idx + lane] = r1*sc; g_q[idx + lane + 32] = r2*sc;
    }
    {
        float k1 = g_k[idx + lane], k2 = g_k[idx + lane + 32];
        float r1 =  k1*cs + k2*sn;
        float r2 = -k1*sn + k2*cs;
        float ss = r1*r1 + r2*r2;
#pragma unroll
        for (int o = 16; o > 0; o >>= 1) ss += __shfl_xor_sync(0xffffffffu, ss, o);
        float sc = rsqrtf(ss * (1.f/64.f) + 1e-6f);
        g_k[idx + lane] = r1*sc; g_k[idx + lane + 32] = r2*sc;
    }
}

// ---------------- 4) flash attention, fp32, BM=BN=64, 64 thr, 8x8 tiles ----
// Row-major swizzled tiles: row stride 64 floats; 16B chunk i of row goes to
// physical chunk (i ^ (row>>3)). Readers with key (row>>3) get conflict-free
// access. Q/K/V loaded by cp.async (K with swizzled dst), P stored as float4.
#define ATTN_SMEM (4*64*64*4)   // Qs, Ks, Ps, Vs = 64KB

__global__ __launch_bounds__(64) void attn_kernel(const int* __restrict__ wsp) {
    extern __shared__ float smf[];
    float* Qs = smf;
    float* Ks = smf + 64*64;
    float* Ps = smf + 2*64*64;
    float* Vs = smf + 3*64*64;

    const int qt = (TT/64 - 1) - blockIdx.x;   // heavy blocks launch first
    const int h = blockIdx.y, b = blockIdx.z;
    const int tid = threadIdx.x;
    const int ty = tid >> 3;       // 0..7 -> 8 q rows
    const int tx = tid & 7;        // 0..7 -> 8 cols
    const int q0 = qt * 64;

    int wsv = wsp ? *wsp : -1;
    const bool use_w = (wsv >= 0) && (wsv < TT - 1);
    int jt0 = 0;
    if (use_w) {
        int lo = q0 - wsv - 63;
        if (lo > 0) jt0 = (lo + 63) >> 6;
    }

    const int hoff = h*64;
    const int key  = (tid >> 3) & 7;   // swizzle key for row `tid`

    const uint32_t qb = (uint32_t)__cvta_generic_to_shared(Qs) + tid*256;
    const uint32_t kb = (uint32_t)__cvta_generic_to_shared(Ks) + tid*256;
    const uint32_t vb = (uint32_t)__cvta_generic_to_shared(Vs) + tid*256;

    // prologue: Q (swizzled) + K[jt0] (swizzled, with stationary shift) as one group
    {
        const float* qsrc = g_q + ((size_t)(b*TT + q0 + tid))*CC + hoff;
#pragma unroll
        for (int i = 0; i < 16; i++) cp_async16(qb + ((i ^ key)*16), qsrc + i*4);
        int pos = jt0*64 + tid;
        int srcpos = (pos > 0) ? pos - 1 : 0;
        const float* k1 = g_k + ((size_t)(b*TT + pos))*CC + hoff;     // d < 32
        const float* k2 = g_k + ((size_t)(b*TT + srcpos))*CC + hoff;  // d >= 32
#pragma unroll
        for (int i = 0; i < 8; i++)  cp_async16(kb + ((i ^ key)*16), k1 + i*4);
#pragma unroll
        for (int i = 8; i < 16; i++) cp_async16(kb + ((i ^ key)*16), k2 + i*4);
        cp_commit();
    }

    float o[8][8];
    float mi[8], li[8];
#pragma unroll
    for (int r = 0; r < 8; r++) {
        mi[r] = -1e30f; li[r] = 0.f;
#pragma unroll
        for (int c = 0; c < 8; c++) o[r][c] = 0.f;
    }

    for (int jt = jt0; jt <= qt; jt++) {
        const int kv0 = jt * 64;
        cp_wait0();          // K[jt] (and Q on first iter) arrived
        __syncthreads();     // K visible; previous PV done (Vs, Ps free)

        // issue V[jt] (plain layout; reads are broadcast so no swizzle needed)
        {
            const float* vsrc = g_v + ((size_t)(b*TT + kv0 + tid))*CC + hoff;
#pragma unroll
            for (int i = 0; i < 16; i++) cp_async16(vb + i*16, vsrc + i*4);
            cp_commit();
        }

        // S = Q K^T (8x8 per thread, swizzled reads)
        float s[8][8];
#pragma unroll
        for (int r = 0; r < 8; r++)
#pragma unroll
            for (int c = 0; c < 8; c++) s[r][c] = 0.f;
#pragma unroll
        for (int d4 = 0; d4 < 16; d4++) {
            float4 k4[8];
#pragma unroll
            for (int c = 0; c < 8; c++)
                k4[c] = *(const float4*)(Ks + (tx*8 + c)*64 + ((d4 ^ tx)*4));
#pragma unroll
            for (int r = 0; r < 8; r++) {
                float4 q = *(const float4*)(Qs + (ty*8 + r)*64 + ((d4 ^ ty)*4));
#pragma unroll
                for (int c = 0; c < 8; c++)
                    s[r][c] += q.x*k4[c].x + q.y*k4[c].y + q.z*k4[c].z + q.w*k4[c].w;
            }
        }

        // mask + scale + online softmax
#pragma unroll
        for (int r = 0; r < 8; r++) {
            int qi = q0 + ty*8 + r;
#pragma unroll
            for (int c = 0; c < 8; c++) {
                int kj = kv0 + tx*8 + c;
                bool ok = (kj <= qi) && (!use_w || (qi - kj) <= wsv);
                s[r][c] = ok ? s[r][c]*0.125f : -1e30f;
            }
            float mx = s[r][0];
#pragma unroll
            for (int c = 1; c < 8; c++) mx = fmaxf(mx, s[r][c]);
            mx = fmaxf(mx, __shfl_xor_sync(0xffffffffu, mx, 1));
            mx = fmaxf(mx, __shfl_xor_sync(0xffffffffu, mx, 2));
            mx = fmaxf(mx, __shfl_xor_sync(0xffffffffu, mx, 4));
            float mnew = fmaxf(fmaxf(mi[r], mx), -1e29f);
            float corr = __expf(mi[r] - mnew);
            float sum = 0.f;
#pragma unroll
            for (int c = 0; c < 8; c++) {
                float p = __expf(s[r][c] - mnew);
                s[r][c] = p; sum += p;
            }
            sum += __shfl_xor_sync(0xffffffffu, sum, 1);
            sum += __shfl_xor_sync(0xffffffffu, sum, 2);
            sum += __shfl_xor_sync(0xffffffffu, sum, 4);
            li[r] = li[r]*corr + sum;
            mi[r] = mnew;
#pragma unroll
            for (int c = 0; c < 8; c++) o[r][c] *= corr;
        }
        __syncthreads();     // S-reads of Ks done; P-write region free

        // write P row-major swizzled (float4)
#pragma unroll
        for (int r = 0; r < 8; r++) {
            float* prow = Ps + (ty*8 + r)*64;
            float4 w0 = {s[r][0], s[r][1], s[r][2], s[r][3]};
            float4 w1 = {s[r][4], s[r][5], s[r][6], s[r][7]};
            *(float4*)(prow + (((tx*2    ) ^ ty)*4)) = w0;
            *(float4*)(prow + (((tx*2 + 1) ^ ty)*4)) = w1;
        }

        // prefetch K[jt+1] (hidden behind PV)
        if (jt < qt) {
            int pos = kv0 + 64 + tid;
            const float* k1 = g_k + ((size_t)(b*TT + pos))*CC + hoff;
            const float* k2 = g_k + ((size_t)(b*TT + pos - 1))*CC + hoff;
#pragma unroll
            for (int i = 0; i < 8; i++)  cp_async16(kb + ((i ^ key)*16), k1 + i*4);
#pragma unroll
            for (int i = 8; i < 16; i++) cp_async16(kb + ((i ^ key)*16), k2 + i*4);
            cp_commit();
            cp_wait1();      // V[jt] done (K[jt+1] may stay in flight)
        } else {
            cp_wait0();      // V[jt] done
        }
        __syncthreads();     // P + V visible

        // O += P V (8x8 per thread)
#pragma unroll
        for (int n4 = 0; n4 < 16; n4++) {
            float4 v0[4], v1[4];
#pragma unroll
            for (int j = 0; j < 4; j++) {
                const float* vrow = Vs + (n4*4 + j)*64 + tx*8;
                v0[j] = *(const float4*)vrow;
                v1[j] = *(const float4*)(vrow + 4);
            }
#pragma unroll
            for (int r = 0; r < 8; r++) {
                float4 p = *(const float4*)(Ps + (ty*8 + r)*64 + ((n4 ^ ty)*4));
                float pr[4] = {p.x, p.y, p.z, p.w};
#pragma unroll
                for (int j = 0; j < 4; j++) {
                    o[r][0] += pr[j]*v0[j].x; o[r][1] += pr[j]*v0[j].y;
                    o[r][2] += pr[j]*v0[j].z; o[r][3] += pr[j]*v0[j].w;
                    o[r][4] += pr[j]*v1[j].x; o[r][5] += pr[j]*v1[j].y;
                    o[r][6] += pr[j]*v1[j].z; o[r][7] += pr[j]*v1[j].w;
                }
            }
        }
    }

    // epilogue: normalize, apply attn gate, write y
#pragma unroll
    for (int r = 0; r < 8; r++) {
        int qi = q0 + ty*8 + r;
        float g = g_ga[(size_t)(b*TT + qi)*HH + h];
        float inv = g / li[r];
        float* dst = g_y + ((size_t)(b*TT + qi))*CC + hoff + tx*8;
        float4 w0 = {o[r][0]*inv, o[r][1]*inv, o[r][2]*inv, o[r][3]*inv};
        float4 w1 = {o[r][4]*inv, o[r][5]*inv, o[r][6]*inv, o[r][7]*inv};
        *(float4*)dst = w0;
        *(float4*)(dst + 4) = w1;
    }
}

// ---------------- launch ----------------------------------------------------
extern "C" void kernel_launch(void* const* d_in, const int* in_sizes, int n_in,
                              void* d_out, int out_size) {
    const float* x    = (const float*)d_in[0];
    const float* ve   = (const float*)d_in[1];
    const float* cosb = (const float*)d_in[2];
    const float* sinb = (const float*)d_in[3];
    const float* cqw  = (const float*)d_in[4];
    const float* ckw  = (const float*)d_in[5];
    const float* cvw  = (const float*)d_in[6];
    const float* cpw  = (const float*)d_in[7];
    const float* vgw  = (const float*)d_in[8];
    const float* agw  = (const float*)d_in[9];
    const float* qm   = (const float*)d_in[10];
    const float* km   = (const float*)d_in[11];
    const float* vm   = (const float*)d_in[12];
    const int*   wsp  = (n_in > 13) ? (const int*)d_in[13] : nullptr;
    float* out = (float*)d_out;

    float *pqw, *pkw, *pvw, *pq, *pk, *pv, *py;
    cudaGetSymbolAddress((void**)&pqw, g_qw);
    cudaGetSymbolAddress((void**)&pkw, g_kw);
    cudaGetSymbolAddress((void**)&pvw, g_vw);
    cudaGetSymbolAddress((void**)&pq,  g_q);
    cudaGetSymbolAddress((void**)&pk,  g_k);
    cudaGetSymbolAddress((void**)&pv,  g_v);
    cudaGetSymbolAddress((void**)&py,  g_y);

    // 1) fuse mixes into weights
    fuse_kernel<<<dim3(CC, 3), 256>>>(cqw, ckw, cvw, qm, km, vm);

    // 2) QKV projections (one launch, z selects problem)
    gemm_nt_kernel<<<dim3(NROWS/128, CC/128, 3), 256>>>(x, pqw, pq, pkw, pk, pvw, pv, CC);

    // 3) gates + rope + rmsnorm
    post_kernel<<<(NROWS*HH*32)/256, 256>>>(x, ve, cosb, sinb, vgw, agw);

    // 4) flash attention
    cudaFuncSetAttribute(attn_kernel, cudaFuncAttributeMaxDynamicSharedMemorySize, ATTN_SMEM);
    attn_kernel<<<dim3(TT/64, HH, BB), 64, ATTN_SMEM>>>(wsp);

    // 5) output projection
    gemm_nt_kernel<<<dim3(NROWS/128, CC/128, 1), 256>>>(py, cpw, out, cpw, out, cpw, out, CC);
}

// round 6
// speedup vs baseline: 2.0025x; 2.0025x over previous
#include <cuda_runtime.h>
#include <cstdint>
#include <cstddef>
#include <math.h>

#define BB 2
#define TT 2048
#define CC 1024
#define HH 16
#define NROWS (BB*TT)   // 4096

// ---------------- scratch (static device allocations; no cudaMalloc) -------
__device__ float g_qw[CC*CC];
__device__ float g_kw[CC*CC];
__device__ float g_vw[CC*CC];
__device__ float g_q[NROWS*CC];
__device__ float g_k[NROWS*CC];
__device__ float g_v[NROWS*CC];
__device__ float g_y[NROWS*CC];
__device__ float g_ga[NROWS*HH];

__device__ __forceinline__ void cp_async16(uint32_t saddr, const void* g) {
    asm volatile("cp.async.cg.shared.global [%0], [%1], 16;\n" :: "r"(saddr), "l"(g));
}
__device__ __forceinline__ void cp_commit() {
    asm volatile("cp.async.commit_group;\n");
}
__device__ __forceinline__ void cp_wait0() {
    asm volatile("cp.async.wait_group 0;\n");
}
__device__ __forceinline__ uint32_t f2tf32(float x) {
    uint32_t r;
    asm("cvt.rna.tf32.f32 %0, %1;" : "=r"(r) : "f"(x));
    return r;
}
__device__ __forceinline__ void mma_tf32(float c[4], uint32_t a0, uint32_t a1,
                                         uint32_t a2, uint32_t a3,
                                         uint32_t b0, uint32_t b1) {
    asm volatile(
        "mma.sync.aligned.m16n8k8.row.col.f32.tf32.tf32.f32 "
        "{%0,%1,%2,%3}, {%4,%5,%6,%7}, {%8,%9}, {%0,%1,%2,%3};"
        : "+f"(c[0]), "+f"(c[1]), "+f"(c[2]), "+f"(c[3])
        : "r"(a0), "r"(a1), "r"(a2), "r"(a3), "r"(b0), "r"(b1));
}

// ---------------- 1) fuse mix into weights ---------------------------------
__global__ void fuse_kernel(const float* __restrict__ cq, const float* __restrict__ ck,
                            const float* __restrict__ cv, const float* __restrict__ qm,
                            const float* __restrict__ km, const float* __restrict__ vm) {
    int row = blockIdx.x;
    int wi  = blockIdx.y;
    const float* W = (wi == 0) ? cq : (wi == 1) ? ck : cv;
    const float* M = (wi == 0) ? qm : (wi == 1) ? km : vm;
    float* O       = (wi == 0) ? g_qw : (wi == 1) ? g_kw : g_vw;
    int h = row >> 6, d = row & 63;
    float mx[16];
#pragma unroll
    for (int m = 0; m < 16; m++) mx[m] = M[h*16 + m];
    for (int c = threadIdx.x; c < CC; c += blockDim.x) {
        float s = 0.f;
#pragma unroll
        for (int m = 0; m < 16; m++) s += mx[m] * W[(m*64 + d)*CC + c];
        O[row*CC + c] = s;
    }
}

// ---------------- 2) NT GEMM via tf32 mma.sync ------------------------------
// C[i][j] = sum_k A[i][k]*B[j][k].  Block 128x128, BK=16, 8 warps (64x32 each).
// smem layout [k][m] pad 136 -> fragment LDS bank = (8k+m)%32, conflict-free.
__global__ __launch_bounds__(256, 2) void gemm_tf32_kernel(
    const float* __restrict__ A,
    const float* __restrict__ B0, float* __restrict__ C0,
    const float* __restrict__ B1, float* __restrict__ C1,
    const float* __restrict__ B2, float* __restrict__ C2,
    int K) {
    const float* Bm = (blockIdx.z == 0) ? B0 : (blockIdx.z == 1) ? B1 : B2;
    float*       Cm = (blockIdx.z == 0) ? C0 : (blockIdx.z == 1) ? C1 : C2;
    const int N = CC;

    __shared__ uint32_t As[2][16][136];
    __shared__ uint32_t Bs[2][16][136];

    const int tid  = threadIdx.x;
    const int lane = tid & 31;
    const int warp = tid >> 5;
    const int wr = warp & 1;          // 0..1 -> 64-row strip
    const int wc = warp >> 1;         // 0..3 -> 32-col strip
    const int g  = lane >> 2;         // 0..7
    const int l4 = lane & 3;          // 0..3
    const int brow = blockIdx.x * 128, bcol = blockIdx.y * 128;

    // loader mapping: row = tid&127, k-offset = (tid>>7)*8
    const int lr = tid & 127;
    const int lk = (tid >> 7) * 8;
    const float* Abase = A  + (size_t)(brow + lr) * K + lk;
    const float* Bbase = Bm + (size_t)(bcol + lr) * K + lk;

    float acc[4][4][4];
#pragma unroll
    for (int mi = 0; mi < 4; mi++)
#pragma unroll
        for (int ni = 0; ni < 4; ni++)
#pragma unroll
            for (int r = 0; r < 4; r++) acc[mi][ni][r] = 0.f;

    // prologue: stage 0
    {
        float4 a0 = *(const float4*)Abase;
        float4 a1 = *(const float4*)(Abase + 4);
        float4 b0 = *(const float4*)Bbase;
        float4 b1 = *(const float4*)(Bbase + 4);
        As[0][lk+0][lr] = f2tf32(a0.x); As[0][lk+1][lr] = f2tf32(a0.y);
        As[0][lk+2][lr] = f2tf32(a0.z); As[0][lk+3][lr] = f2tf32(a0.w);
        As[0][lk+4][lr] = f2tf32(a1.x); As[0][lk+5][lr] = f2tf32(a1.y);
        As[0][lk+6][lr] = f2tf32(a1.z); As[0][lk+7][lr] = f2tf32(a1.w);
        Bs[0][lk+0][lr] = f2tf32(b0.x); Bs[0][lk+1][lr] = f2tf32(b0.y);
        Bs[0][lk+2][lr] = f2tf32(b0.z); Bs[0][lk+3][lr] = f2tf32(b0.w);
        Bs[0][lk+4][lr] = f2tf32(b1.x); Bs[0][lk+5][lr] = f2tf32(b1.y);
        Bs[0][lk+6][lr] = f2tf32(b1.z); Bs[0][lk+7][lr] = f2tf32(b1.w);
    }
    __syncthreads();

    int p = 0;
    for (int kk = 0; kk < K; kk += 16) {
        const bool has = (kk + 16) < K;
        float4 an0, an1, bn0, bn1;
        if (has) {
            an0 = *(const float4*)(Abase + kk + 16);
            an1 = *(const float4*)(Abase + kk + 20);
            bn0 = *(const float4*)(Bbase + kk + 16);
            bn1 = *(const float4*)(Bbase + kk + 20);
        }
#pragma unroll
        for (int ks = 0; ks < 2; ks++) {
            const int k0 = ks*8;
            uint32_t bf[4][2];
#pragma unroll
            for (int ni = 0; ni < 4; ni++) {
                int n0 = wc*32 + ni*8;
                bf[ni][0] = Bs[p][k0 + l4    ][n0 + g];
                bf[ni][1] = Bs[p][k0 + l4 + 4][n0 + g];
            }
#pragma unroll
            for (int mi = 0; mi < 4; mi++) {
                int m0 = wr*64 + mi*16;
                uint32_t a0 = As[p][k0 + l4    ][m0 + g];
                uint32_t a1 = As[p][k0 + l4    ][m0 + g + 8];
                uint32_t a2 = As[p][k0 + l4 + 4][m0 + g];
                uint32_t a3 = As[p][k0 + l4 + 4][m0 + g + 8];
#pragma unroll
                for (int ni = 0; ni < 4; ni++)
                    mma_tf32(acc[mi][ni], a0, a1, a2, a3, bf[ni][0], bf[ni][1]);
            }
        }
        if (has) {
            int q = p ^ 1;
            As[q][lk+0][lr] = f2tf32(an0.x); As[q][lk+1][lr] = f2tf32(an0.y);
            As[q][lk+2][lr] = f2tf32(an0.z); As[q][lk+3][lr] = f2tf32(an0.w);
            As[q][lk+4][lr] = f2tf32(an1.x); As[q][lk+5][lr] = f2tf32(an1.y);
            As[q][lk+6][lr] = f2tf32(an1.z); As[q][lk+7][lr] = f2tf32(an1.w);
            Bs[q][lk+0][lr] = f2tf32(bn0.x); Bs[q][lk+1][lr] = f2tf32(bn0.y);
            Bs[q][lk+2][lr] = f2tf32(bn0.z); Bs[q][lk+3][lr] = f2tf32(bn0.w);
            Bs[q][lk+4][lr] = f2tf32(bn1.x); Bs[q][lk+5][lr] = f2tf32(bn1.y);
            Bs[q][lk+6][lr] = f2tf32(bn1.z); Bs[q][lk+7][lr] = f2tf32(bn1.w);
            __syncthreads();
            p = q;
        }
    }

    // epilogue
#pragma unroll
    for (int mi = 0; mi < 4; mi++) {
#pragma unroll
        for (int ni = 0; ni < 4; ni++) {
            int row0 = brow + wr*64 + mi*16 + g;
            int col  = bcol + wc*32 + ni*8 + 2*l4;
            float2 w0 = {acc[mi][ni][0], acc[mi][ni][1]};
            float2 w1 = {acc[mi][ni][2], acc[mi][ni][3]};
            *(float2*)(Cm + (size_t)row0 * N + col)       = w0;
            *(float2*)(Cm + (size_t)(row0 + 8) * N + col) = w1;
        }
    }
}

// ---------------- 3) gates + RoPE + RMSNorm (one warp per (b,t,h)) ----------
__global__ void post_kernel(const float* __restrict__ x, const float* __restrict__ ve,
                            const float* __restrict__ cosb, const float* __restrict__ sinb,
                            const float* __restrict__ vgw, const float* __restrict__ agw) {
    int gw   = (blockIdx.x * blockDim.x + threadIdx.x) >> 5;
    int lane = threadIdx.x & 31;
    if (gw >= NROWS*HH) return;
    int h  = gw % HH;
    int bt = gw / HH;
    int t  = bt % TT;
    size_t xbase = (size_t)bt * CC;

    float gv = x[xbase + lane] * vgw[h*32 + lane];
#pragma unroll
    for (int o = 16; o > 0; o >>= 1) gv += __shfl_xor_sync(0xffffffffu, gv, o);
    float gate_v = 2.f / (1.f + __expf(-gv));

    float ga = (lane < 12) ? x[xbase + lane] * agw[h*12 + lane] : 0.f;
#pragma unroll
    for (int o = 16; o > 0; o >>= 1) ga += __shfl_xor_sync(0xffffffffu, ga, o);
    if (lane == 0) g_ga[(size_t)bt*HH + h] = 1.f / (1.f + __expf(-ga));

    size_t idx = xbase + h*64;
    g_v[idx + lane]      += gate_v * ve[idx + lane];
    g_v[idx + lane + 32] += gate_v * ve[idx + lane + 32];

    float cs = cosb[t*32 + lane], sn = sinb[t*32 + lane];
    {
        float q1 = g_q[idx + lane], q2 = g_q[idx + lane + 32];
        float r1 =  q1*cs + q2*sn;
        float r2 = -q1*sn + q2*cs;
        float ss = r1*r1 + r2*r2;
#pragma unroll
        for (int o = 16; o > 0; o >>= 1) ss += __shfl_xor_sync(0xffffffffu, ss, o);
        float sc = rsqrtf(ss * (1.f/64.f) + 1e-6f);
        g_q[idx + lane] = r1*sc; g_q[idx + lane + 32] = r2*sc;
    }
    {
        float k1 = g_k[idx + lane], k2 = g_k[idx + lane + 32];
        float r1 =  k1*cs + k2*sn;
        float r2 = -k1*sn + k2*cs;
        float ss = r1*r1 + r2*r2;
#pragma unroll
        for (int o = 16; o > 0; o >>= 1) ss += __shfl_xor_sync(0xffffffffu, ss, o);
        float sc = rsqrtf(ss * (1.f/64.f) + 1e-6f);
        g_k[idx + lane] = r1*sc; g_k[idx + lane + 32] = r2*sc;
    }
}

// ---------------- 4) flash attention, fp32, BM=BN=64 (R3 proven version) ---
#define SMP 68
#define ATTN_SMEM (5*64*SMP*4)   // Qs, Ks, Ps, Vs x2

__global__ __launch_bounds__(128) void attn_kernel(const int* __restrict__ wsp) {
    extern __shared__ float smf[];
    float* Qs  = smf;              // [d][m]
    float* Ks  = Qs  + 64*SMP;     // [d][n]
    float* Ps  = Ks  + 64*SMP;     // [n][m]
    float* Vs0 = Ps  + 64*SMP;     // [n][d]
    float* Vs1 = Vs0 + 64*SMP;

    const int qt = blockIdx.x, h = blockIdx.y, b = blockIdx.z;
    const int tid = threadIdx.x;
    const int tr = tid >> 3;       // 0..15 -> 4 q rows
    const int tc = tid & 7;        // 0..7  -> 8 cols
    const int q0 = qt * 64;

    int wsv = wsp ? *wsp : -1;
    const bool use_w = (wsv >= 0) && (wsv < TT - 1);
    int jt0 = 0;
    if (use_w) {
        int lo = q0 - wsv - 63;
        if (lo > 0) jt0 = (lo + 63) >> 6;
    }

    const int m    = tid >> 1;
    const int half = tid & 1;
    const int hoff = h*64 + half*32;

    // load Q tile (transposed into [d][m])
    {
        const float* src = g_q + ((size_t)(b*TT + q0 + m))*CC + hoff;
#pragma unroll
        for (int i = 0; i < 8; i++) {
            float4 v = *(const float4*)(src + i*4);
            int d = half*32 + i*4;
            Qs[(d+0)*SMP + m] = v.x; Qs[(d+1)*SMP + m] = v.y;
            Qs[(d+2)*SMP + m] = v.z; Qs[(d+3)*SMP + m] = v.w;
        }
    }

    // prologue: K tile jt0 -> regs, V tile jt0 -> cp.async into Vs0
    float4 kreg[8];
    {
        int pos = jt0*64 + m;
        int srcpos = (half == 0) ? pos : (pos > 0 ? pos - 1 : 0);
        const float* ks = g_k + ((size_t)(b*TT + srcpos))*CC + hoff;
#pragma unroll
        for (int i = 0; i < 8; i++) kreg[i] = *(const float4*)(ks + i*4);
        const float* vsrc = g_v + ((size_t)(b*TT + pos))*CC + hoff;
        uint32_t vdst = (uint32_t)__cvta_generic_to_shared(Vs0 + m*SMP + half*32);
#pragma unroll
        for (int i = 0; i < 8; i++) cp_async16(vdst + i*16, vsrc + i*4);
        cp_commit();
    }

    float o[4][8];
    float mi[4], li[4];
#pragma unroll
    for (int r = 0; r < 4; r++) {
        mi[r] = -1e30f; li[r] = 0.f;
#pragma unroll
        for (int c = 0; c < 8; c++) o[r][c] = 0.f;
    }

    float* Vcur = Vs0;
    float* Vnxt = Vs1;

    for (int jt = jt0; jt <= qt; jt++) {
        const int kv0 = jt * 64;
        cp_wait0();
        // store staged K (transposed)
#pragma unroll
        for (int i = 0; i < 8; i++) {
            int d = half*32 + i*4;
            Ks[(d+0)*SMP + m] = kreg[i].x; Ks[(d+1)*SMP + m] = kreg[i].y;
            Ks[(d+2)*SMP + m] = kreg[i].z; Ks[(d+3)*SMP + m] = kreg[i].w;
        }
        __syncthreads();

        // S = Q K^T
        float s[4][8];
#pragma unroll
        for (int r = 0; r < 4; r++)
#pragma unroll
            for (int c = 0; c < 8; c++) s[r][c] = 0.f;
#pragma unroll 16
        for (int d = 0; d < 64; d++) {
            float4 a  = *(const float4*)(Qs + d*SMP + tr*4);
            float4 b0 = *(const float4*)(Ks + d*SMP + tc*8);
            float4 b1 = *(const float4*)(Ks + d*SMP + tc*8 + 4);
            float ar[4] = {a.x, a.y, a.z, a.w};
            float br[8] = {b0.x,b0.y,b0.z,b0.w,b1.x,b1.y,b1.z,b1.w};
#pragma unroll
            for (int r = 0; r < 4; r++)
#pragma unroll
                for (int c = 0; c < 8; c++) s[r][c] += ar[r]*br[c];
        }
        // mask + scale
#pragma unroll
        for (int r = 0; r < 4; r++) {
            int qi = q0 + tr*4 + r;
#pragma unroll
            for (int c = 0; c < 8; c++) {
                int kj = kv0 + tc*8 + c;
                bool ok = (kj <= qi) && (!use_w || (qi - kj) <= wsv);
                s[r][c] = ok ? s[r][c]*0.125f : -1e30f;
            }
        }
        // online softmax
#pragma unroll
        for (int r = 0; r < 4; r++) {
            float mx = s[r][0];
#pragma unroll
            for (int c = 1; c < 8; c++) mx = fmaxf(mx, s[r][c]);
            mx = fmaxf(mx, __shfl_xor_sync(0xffffffffu, mx, 1));
            mx = fmaxf(mx, __shfl_xor_sync(0xffffffffu, mx, 2));
            mx = fmaxf(mx, __shfl_xor_sync(0xffffffffu, mx, 4));
            float mnew = fmaxf(fmaxf(mi[r], mx), -1e29f);
            float corr = __expf(mi[r] - mnew);
            float sum = 0.f;
#pragma unroll
            for (int c = 0; c < 8; c++) {
                float p = __expf(s[r][c] - mnew);
                s[r][c] = p; sum += p;
            }
            sum += __shfl_xor_sync(0xffffffffu, sum, 1);
            sum += __shfl_xor_sync(0xffffffffu, sum, 2);
            sum += __shfl_xor_sync(0xffffffffu, sum, 4);
            li[r] = li[r]*corr + sum;
            mi[r] = mnew;
#pragma unroll
            for (int c = 0; c < 8; c++) o[r][c] *= corr;
#pragma unroll
            for (int c = 0; c < 8; c++)
                Ps[(tc*8 + c)*SMP + tr*4 + r] = s[r][c];
        }

        // prefetch next tile (hidden behind PV)
        if (jt < qt) {
            int pos = kv0 + 64 + m;
            int srcpos = (half == 0) ? pos : (pos - 1);
            const float* ks = g_k + ((size_t)(b*TT + srcpos))*CC + hoff;
#pragma unroll
            for (int i = 0; i < 8; i++) kreg[i] = *(const float4*)(ks + i*4);
            const float* vsrc = g_v + ((size_t)(b*TT + pos))*CC + hoff;
            uint32_t vdst = (uint32_t)__cvta_generic_to_shared(Vnxt + m*SMP + half*32);
#pragma unroll
            for (int i = 0; i < 8; i++) cp_async16(vdst + i*16, vsrc + i*4);
            cp_commit();
        }
        __syncthreads();

        // O += P V
#pragma unroll 16
        for (int n = 0; n < 64; n++) {
            float4 p  = *(const float4*)(Ps + n*SMP + tr*4);
            float4 v0 = *(const float4*)(Vcur + n*SMP + tc*8);
            float4 v1 = *(const float4*)(Vcur + n*SMP + tc*8 + 4);
            float pr[4] = {p.x, p.y, p.z, p.w};
            float vr[8] = {v0.x,v0.y,v0.z,v0.w,v1.x,v1.y,v1.z,v1.w};
#pragma unroll
            for (int r = 0; r < 4; r++)
#pragma unroll
                for (int c = 0; c < 8; c++) o[r][c] += pr[r]*vr[c];
        }
        { float* t = Vcur; Vcur = Vnxt; Vnxt = t; }
    }

    // epilogue: normalize, apply attn gate, write y
#pragma unroll
    for (int r = 0; r < 4; r++) {
        int qi = q0 + tr*4 + r;
        float g = g_ga[(size_t)(b*TT + qi)*HH + h];
        float inv = g / li[r];
        float* dst = g_y + ((size_t)(b*TT + qi))*CC + h*64 + tc*8;
        float4 w0 = {o[r][0]*inv, o[r][1]*inv, o[r][2]*inv, o[r][3]*inv};
        float4 w1 = {o[r][4]*inv, o[r][5]*inv, o[r][6]*inv, o[r][7]*inv};
        *(float4*)dst = w0;
        *(float4*)(dst + 4) = w1;
    }
}

// ---------------- launch ----------------------------------------------------
extern "C" void kernel_launch(void* const* d_in, const int* in_sizes, int n_in,
                              void* d_out, int out_size) {
    const float* x    = (const float*)d_in[0];
    const float* ve   = (const float*)d_in[1];
    const float* cosb = (const float*)d_in[2];
    const float* sinb = (const float*)d_in[3];
    const float* cqw  = (const float*)d_in[4];
    const float* ckw  = (const float*)d_in[5];
    const float* cvw  = (const float*)d_in[6];
    const float* cpw  = (const float*)d_in[7];
    const float* vgw  = (const float*)d_in[8];
    const float* agw  = (const float*)d_in[9];
    const float* qm   = (const float*)d_in[10];
    const float* km   = (const float*)d_in[11];
    const float* vm   = (const float*)d_in[12];
    const int*   wsp  = (n_in > 13) ? (const int*)d_in[13] : nullptr;
    float* out = (float*)d_out;

    float *pqw, *pkw, *pvw, *pq, *pk, *pv, *py;
    cudaGetSymbolAddress((void**)&pqw, g_qw);
    cudaGetSymbolAddress((void**)&pkw, g_kw);
    cudaGetSymbolAddress((void**)&pvw, g_vw);
    cudaGetSymbolAddress((void**)&pq,  g_q);
    cudaGetSymbolAddress((void**)&pk,  g_k);
    cudaGetSymbolAddress((void**)&pv,  g_v);
    cudaGetSymbolAddress((void**)&py,  g_y);

    // 1) fuse mixes into weights
    fuse_kernel<<<dim3(CC, 3), 256>>>(cqw, ckw, cvw, qm, km, vm);

    // 2) QKV projections (tf32 tensor cores, one launch)
    gemm_tf32_kernel<<<dim3(NROWS/128, CC/128, 3), 256>>>(x, pqw, pq, pkw, pk, pvw, pv, CC);

    // 3) gates + rope + rmsnorm
    post_kernel<<<(NROWS*HH*32)/256, 256>>>(x, ve, cosb, sinb, vgw, agw);

    // 4) flash attention
    cudaFuncSetAttribute(attn_kernel, cudaFuncAttributeMaxDynamicSharedMemorySize, ATTN_SMEM);
    attn_kernel<<<dim3(TT/64, HH, BB), 128, ATTN_SMEM>>>(wsp);

    // 5) output projection (tf32)
    gemm_tf32_kernel<<<dim3(NROWS/128, CC/128, 1), 256>>>(py, cpw, out, cpw, out, cpw, out, CC);
}

// round 7
// speedup vs baseline: 3.5279x; 1.7617x over previous
#include <cuda_runtime.h>
#include <cstdint>
#include <cstddef>
#include <math.h>

#define BB 2
#define TT 2048
#define CC 1024
#define HH 16
#define NROWS (BB*TT)   // 4096

// ---------------- scratch (static device allocations; no cudaMalloc) -------
__device__ float g_qw[CC*CC];
__device__ float g_kw[CC*CC];
__device__ float g_vw[CC*CC];
__device__ float g_q[NROWS*CC];
__device__ float g_k[NROWS*CC];
__device__ float g_v[NROWS*CC];
__device__ float g_y[NROWS*CC];
__device__ float g_ga[NROWS*HH];

__device__ __forceinline__ void cp_async16(uint32_t saddr, const void* g) {
    asm volatile("cp.async.cg.shared.global [%0], [%1], 16;\n" :: "r"(saddr), "l"(g));
}
__device__ __forceinline__ void cp_commit() {
    asm volatile("cp.async.commit_group;\n");
}
__device__ __forceinline__ void cp_wait0() {
    asm volatile("cp.async.wait_group 0;\n");
}
__device__ __forceinline__ void cp_wait1() {
    asm volatile("cp.async.wait_group 1;\n");
}
__device__ __forceinline__ uint32_t f2tf32(float x) {
    uint32_t r;
    asm("cvt.rna.tf32.f32 %0, %1;" : "=r"(r) : "f"(x));
    return r;
}
__device__ __forceinline__ void mma_tf32(float c[4], uint32_t a0, uint32_t a1,
                                         uint32_t a2, uint32_t a3,
                                         uint32_t b0, uint32_t b1) {
    asm volatile(
        "mma.sync.aligned.m16n8k8.row.col.f32.tf32.tf32.f32 "
        "{%0,%1,%2,%3}, {%4,%5,%6,%7}, {%8,%9}, {%0,%1,%2,%3};"
        : "+f"(c[0]), "+f"(c[1]), "+f"(c[2]), "+f"(c[3])
        : "r"(a0), "r"(a1), "r"(a2), "r"(a3), "r"(b0), "r"(b1));
}

// ---------------- 1) fuse mix into weights ---------------------------------
__global__ void fuse_kernel(const float* __restrict__ cq, const float* __restrict__ ck,
                            const float* __restrict__ cv, const float* __restrict__ qm,
                            const float* __restrict__ km, const float* __restrict__ vm) {
    int row = blockIdx.x;
    int wi  = blockIdx.y;
    const float* W = (wi == 0) ? cq : (wi == 1) ? ck : cv;
    const float* M = (wi == 0) ? qm : (wi == 1) ? km : vm;
    float* O       = (wi == 0) ? g_qw : (wi == 1) ? g_kw : g_vw;
    int h = row >> 6, d = row & 63;
    float mx[16];
#pragma unroll
    for (int m = 0; m < 16; m++) mx[m] = M[h*16 + m];
    for (int c = threadIdx.x; c < CC; c += blockDim.x) {
        float s = 0.f;
#pragma unroll
        for (int m = 0; m < 16; m++) s += mx[m] * W[(m*64 + d)*CC + c];
        O[row*CC + c] = s;
    }
}

// ---------------- 2) NT GEMM via tf32 mma.sync (proven R6 version) ----------
__global__ __launch_bounds__(256, 2) void gemm_tf32_kernel(
    const float* __restrict__ A,
    const float* __restrict__ B0, float* __restrict__ C0,
    const float* __restrict__ B1, float* __restrict__ C1,
    const float* __restrict__ B2, float* __restrict__ C2,
    int K) {
    const float* Bm = (blockIdx.z == 0) ? B0 : (blockIdx.z == 1) ? B1 : B2;
    float*       Cm = (blockIdx.z == 0) ? C0 : (blockIdx.z == 1) ? C1 : C2;
    const int N = CC;

    __shared__ uint32_t As[2][16][136];
    __shared__ uint32_t Bs[2][16][136];

    const int tid  = threadIdx.x;
    const int lane = tid & 31;
    const int warp = tid >> 5;
    const int wr = warp & 1;
    const int wc = warp >> 1;
    const int g  = lane >> 2;
    const int l4 = lane & 3;
    const int brow = blockIdx.x * 128, bcol = blockIdx.y * 128;

    const int lr = tid & 127;
    const int lk = (tid >> 7) * 8;
    const float* Abase = A  + (size_t)(brow + lr) * K + lk;
    const float* Bbase = Bm + (size_t)(bcol + lr) * K + lk;

    float acc[4][4][4];
#pragma unroll
    for (int mi = 0; mi < 4; mi++)
#pragma unroll
        for (int ni = 0; ni < 4; ni++)
#pragma unroll
            for (int r = 0; r < 4; r++) acc[mi][ni][r] = 0.f;

    {
        float4 a0 = *(const float4*)Abase;
        float4 a1 = *(const float4*)(Abase + 4);
        float4 b0 = *(const float4*)Bbase;
        float4 b1 = *(const float4*)(Bbase + 4);
        As[0][lk+0][lr] = f2tf32(a0.x); As[0][lk+1][lr] = f2tf32(a0.y);
        As[0][lk+2][lr] = f2tf32(a0.z); As[0][lk+3][lr] = f2tf32(a0.w);
        As[0][lk+4][lr] = f2tf32(a1.x); As[0][lk+5][lr] = f2tf32(a1.y);
        As[0][lk+6][lr] = f2tf32(a1.z); As[0][lk+7][lr] = f2tf32(a1.w);
        Bs[0][lk+0][lr] = f2tf32(b0.x); Bs[0][lk+1][lr] = f2tf32(b0.y);
        Bs[0][lk+2][lr] = f2tf32(b0.z); Bs[0][lk+3][lr] = f2tf32(b0.w);
        Bs[0][lk+4][lr] = f2tf32(b1.x); Bs[0][lk+5][lr] = f2tf32(b1.y);
        Bs[0][lk+6][lr] = f2tf32(b1.z); Bs[0][lk+7][lr] = f2tf32(b1.w);
    }
    __syncthreads();

    int p = 0;
    for (int kk = 0; kk < K; kk += 16) {
        const bool has = (kk + 16) < K;
        float4 an0, an1, bn0, bn1;
        if (has) {
            an0 = *(const float4*)(Abase + kk + 16);
            an1 = *(const float4*)(Abase + kk + 20);
            bn0 = *(const float4*)(Bbase + kk + 16);
            bn1 = *(const float4*)(Bbase + kk + 20);
        }
#pragma unroll
        for (int ks = 0; ks < 2; ks++) {
            const int k0 = ks*8;
            uint32_t bf[4][2];
#pragma unroll
            for (int ni = 0; ni < 4; ni++) {
                int n0 = wc*32 + ni*8;
                bf[ni][0] = Bs[p][k0 + l4    ][n0 + g];
                bf[ni][1] = Bs[p][k0 + l4 + 4][n0 + g];
            }
#pragma unroll
            for (int mi = 0; mi < 4; mi++) {
                int m0 = wr*64 + mi*16;
                uint32_t a0 = As[p][k0 + l4    ][m0 + g];
                uint32_t a1 = As[p][k0 + l4    ][m0 + g + 8];
                uint32_t a2 = As[p][k0 + l4 + 4][m0 + g];
                uint32_t a3 = As[p][k0 + l4 + 4][m0 + g + 8];
#pragma unroll
                for (int ni = 0; ni < 4; ni++)
                    mma_tf32(acc[mi][ni], a0, a1, a2, a3, bf[ni][0], bf[ni][1]);
            }
        }
        if (has) {
            int q = p ^ 1;
            As[q][lk+0][lr] = f2tf32(an0.x); As[q][lk+1][lr] = f2tf32(an0.y);
            As[q][lk+2][lr] = f2tf32(an0.z); As[q][lk+3][lr] = f2tf32(an0.w);
            As[q][lk+4][lr] = f2tf32(an1.x); As[q][lk+5][lr] = f2tf32(an1.y);
            As[q][lk+6][lr] = f2tf32(an1.z); As[q][lk+7][lr] = f2tf32(an1.w);
            Bs[q][lk+0][lr] = f2tf32(bn0.x); Bs[q][lk+1][lr] = f2tf32(bn0.y);
            Bs[q][lk+2][lr] = f2tf32(bn0.z); Bs[q][lk+3][lr] = f2tf32(bn0.w);
            Bs[q][lk+4][lr] = f2tf32(bn1.x); Bs[q][lk+5][lr] = f2tf32(bn1.y);
            Bs[q][lk+6][lr] = f2tf32(bn1.z); Bs[q][lk+7][lr] = f2tf32(bn1.w);
            __syncthreads();
            p = q;
        }
    }

#pragma unroll
    for (int mi = 0; mi < 4; mi++) {
#pragma unroll
        for (int ni = 0; ni < 4; ni++) {
            int row0 = brow + wr*64 + mi*16 + g;
            int col  = bcol + wc*32 + ni*8 + 2*l4;
            float2 w0 = {acc[mi][ni][0], acc[mi][ni][1]};
            float2 w1 = {acc[mi][ni][2], acc[mi][ni][3]};
            *(float2*)(Cm + (size_t)row0 * N + col)       = w0;
            *(float2*)(Cm + (size_t)(row0 + 8) * N + col) = w1;
        }
    }
}

// ---------------- 3) gates + RoPE + RMSNorm; q/k/v pre-rounded to tf32 ------
__global__ void post_kernel(const float* __restrict__ x, const float* __restrict__ ve,
                            const float* __restrict__ cosb, const float* __restrict__ sinb,
                            const float* __restrict__ vgw, const float* __restrict__ agw) {
    int gw   = (blockIdx.x * blockDim.x + threadIdx.x) >> 5;
    int lane = threadIdx.x & 31;
    if (gw >= NROWS*HH) return;
    int h  = gw % HH;
    int bt = gw / HH;
    int t  = bt % TT;
    size_t xbase = (size_t)bt * CC;

    float gv = x[xbase + lane] * vgw[h*32 + lane];
#pragma unroll
    for (int o = 16; o > 0; o >>= 1) gv += __shfl_xor_sync(0xffffffffu, gv, o);
    float gate_v = 2.f / (1.f + __expf(-gv));

    float ga = (lane < 12) ? x[xbase + lane] * agw[h*12 + lane] : 0.f;
#pragma unroll
    for (int o = 16; o > 0; o >>= 1) ga += __shfl_xor_sync(0xffffffffu, ga, o);
    if (lane == 0) g_ga[(size_t)bt*HH + h] = 1.f / (1.f + __expf(-ga));

    size_t idx = xbase + h*64;
    // v += gate_v * ve, rounded to tf32 for the PV mma
    float v1 = g_v[idx + lane]      + gate_v * ve[idx + lane];
    float v2 = g_v[idx + lane + 32] + gate_v * ve[idx + lane + 32];
    g_v[idx + lane]      = __uint_as_float(f2tf32(v1));
    g_v[idx + lane + 32] = __uint_as_float(f2tf32(v2));

    float cs = cosb[t*32 + lane], sn = sinb[t*32 + lane];
    {
        float q1 = g_q[idx + lane], q2 = g_q[idx + lane + 32];
        float r1 =  q1*cs + q2*sn;
        float r2 = -q1*sn + q2*cs;
        float ss = r1*r1 + r2*r2;
#pragma unroll
        for (int o = 16; o > 0; o >>= 1) ss += __shfl_xor_sync(0xffffffffu, ss, o);
        float sc = rsqrtf(ss * (1.f/64.f) + 1e-6f);
        g_q[idx + lane]      = __uint_as_float(f2tf32(r1*sc));
        g_q[idx + lane + 32] = __uint_as_float(f2tf32(r2*sc));
    }
    {
        float k1 = g_k[idx + lane], k2 = g_k[idx + lane + 32];
        float r1 =  k1*cs + k2*sn;
        float r2 = -k1*sn + k2*cs;
        float ss = r1*r1 + r2*r2;
#pragma unroll
        for (int o = 16; o > 0; o >>= 1) ss += __shfl_xor_sync(0xffffffffu, ss, o);
        float sc = rsqrtf(ss * (1.f/64.f) + 1e-6f);
        g_k[idx + lane]      = __uint_as_float(f2tf32(r1*sc));
        g_k[idx + lane + 32] = __uint_as_float(f2tf32(r2*sc));
    }
}

// ---------------- 4) flash attention via tf32 mma, BM=128, BN=64 ------------
// smem: QPs [128][68] (Q then reused for P, warp-private rows),
//       Ks  [2][64][68], Vs [2][64][68]  (double-buffered cp.async)
#define AST 68
#define ATTN_SMEM ((128*AST + 4*64*AST)*4)

__global__ __launch_bounds__(256, 2) void attn_kernel(const int* __restrict__ wsp) {
    extern __shared__ float smf[];
    float* QPs = smf;                       // [128][AST]
    float* Ks  = smf + 128*AST;             // [2][64][AST]
    float* Vs  = Ks  + 2*64*AST;            // [2][64][AST]
    uint32_t* QPu = (uint32_t*)QPs;

    const int qtb = (TT/128 - 1) - blockIdx.x;   // heavy blocks first
    const int h = blockIdx.y, b = blockIdx.z;
    const int tid  = threadIdx.x;
    const int lane = tid & 31;
    const int w    = tid >> 5;      // 0..7
    const int g    = lane >> 2;     // 0..7
    const int l4   = lane & 3;      // 0..3
    const int q0   = qtb * 128;
    const int hoff = h*64;
    const size_t bT = (size_t)b*TT;

    int wsv = wsp ? *wsp : -1;
    const bool use_w = (wsv >= 0) && (wsv < TT - 1);
    int jt0 = 0;
    if (use_w) {
        int lo = q0 - wsv - 63;
        if (lo > 0) jt0 = (lo + 63) >> 6;
    }
    const int jtmax = 2*qtb + 1;

    // ---- prologue: cp.async Q (group 1), then K/V[jt0] (group 2)
    {
        int row = tid >> 1;
        int c0  = (tid & 1) * 8;
        const float* src = g_q + (bT + q0 + row)*CC + hoff;
        uint32_t dst = (uint32_t)__cvta_generic_to_shared(QPs + row*AST);
#pragma unroll
        for (int i = 0; i < 8; i++) cp_async16(dst + (c0 + i)*16, src + (c0 + i)*4);
        cp_commit();
    }
    {
        int r  = tid >> 2;
        int c0 = (tid & 3) * 4;      // chunks c0..c0+3 (of 16)
        int pos = jt0*64 + r;
        int sh  = (pos > 0) ? pos - 1 : 0;
        uint32_t kd = (uint32_t)__cvta_generic_to_shared(Ks + (jt0&1)*64*AST + r*AST);
        uint32_t vd = (uint32_t)__cvta_generic_to_shared(Vs + (jt0&1)*64*AST + r*AST);
        const float* kp = g_k + (bT + pos)*CC + hoff;
        const float* ks = g_k + (bT + sh)*CC + hoff;
        const float* vp = g_v + (bT + pos)*CC + hoff;
#pragma unroll
        for (int i = 0; i < 4; i++) {
            int c = c0 + i;
            const float* kb = (c < 8) ? kp : ks;  // d>=32 uses shifted row
            cp_async16(kd + c*16, kb + c*4);
            cp_async16(vd + c*16, vp + c*4);
        }
        cp_commit();
    }

    // ---- wait for Q, load Q fragments into registers
    uint32_t qa[8][4];
    cp_wait1();
    __syncthreads();
    {
        const float* q0p = QPs + (16*w + g)*AST;
        const float* q1p = QPs + (16*w + g + 8)*AST;
#pragma unroll
        for (int ks = 0; ks < 8; ks++) {
            qa[ks][0] = __float_as_uint(q0p[8*ks + l4]);
            qa[ks][1] = __float_as_uint(q1p[8*ks + l4]);
            qa[ks][2] = __float_as_uint(q0p[8*ks + l4 + 4]);
            qa[ks][3] = __float_as_uint(q1p[8*ks + l4 + 4]);
        }
    }
    __syncwarp();

    float oacc[8][4];
#pragma unroll
    for (int nt = 0; nt < 8; nt++)
#pragma unroll
        for (int r = 0; r < 4; r++) oacc[nt][r] = 0.f;
    float mi0 = -1e30f, mi1 = -1e30f, li0 = 0.f, li1 = 0.f;

    const int wrmin = q0 + 16*w;          // warp's min q row
    const int wrmax = wrmin + 15;
    const int r0g   = wrmin + g;          // this thread's two rows
    const int r1g   = r0g + 8;
    uint32_t* Pw0 = QPu + (16*w + g)*AST;
    uint32_t* Pw1 = QPu + (16*w + g + 8)*AST;

    for (int jt = jt0; jt <= jtmax; jt++) {
        const int kv0 = jt * 64;
        const int buf = jt & 1;
        cp_wait0();
        __syncthreads();

        // prefetch K/V[jt+1] into the other buffer
        if (jt < jtmax) {
            int r  = tid >> 2;
            int c0 = (tid & 3) * 4;
            int pos = kv0 + 64 + r;
            uint32_t kd = (uint32_t)__cvta_generic_to_shared(Ks + (buf^1)*64*AST + r*AST);
            uint32_t vd = (uint32_t)__cvta_generic_to_shared(Vs + (buf^1)*64*AST + r*AST);
            const float* kp = g_k + (bT + pos)*CC + hoff;
            const float* ksh = g_k + (bT + pos - 1)*CC + hoff;
            const float* vp = g_v + (bT + pos)*CC + hoff;
#pragma unroll
            for (int i = 0; i < 4; i++) {
                int c = c0 + i;
                const float* kb = (c < 8) ? kp : ksh;
                cp_async16(kd + c*16, kb + c*4);
                cp_async16(vd + c*16, vp + c*4);
            }
            cp_commit();
        }

        // warp-level dead-tile skip (fully masked for this warp's rows)
        bool dead = (kv0 > wrmax) || (use_w && (kv0 + 63 < wrmin - wsv));
        if (!dead) {
            const float* Kb = Ks + buf*64*AST;
            const float* Vb = Vs + buf*64*AST;

            // S = Q K^T
            float sacc[8][4];
#pragma unroll
            for (int nt = 0; nt < 8; nt++)
#pragma unroll
                for (int r = 0; r < 4; r++) sacc[nt][r] = 0.f;
#pragma unroll
            for (int ks = 0; ks < 8; ks++) {
#pragma unroll
                for (int nt = 0; nt < 8; nt++) {
                    uint32_t b0 = __float_as_uint(Kb[(8*nt + g)*AST + 8*ks + l4]);
                    uint32_t b1 = __float_as_uint(Kb[(8*nt + g)*AST + 8*ks + l4 + 4]);
                    mma_tf32(sacc[nt], qa[ks][0], qa[ks][1], qa[ks][2], qa[ks][3], b0, b1);
                }
            }

            // scale + mask
            const bool full = (kv0 + 63 <= wrmin) &&
                              (!use_w || (wrmax - kv0 <= wsv));
            if (full) {
#pragma unroll
                for (int nt = 0; nt < 8; nt++)
#pragma unroll
                    for (int r = 0; r < 4; r++) sacc[nt][r] *= 0.125f;
            } else {
#pragma unroll
                for (int nt = 0; nt < 8; nt++) {
                    int c0 = kv0 + 8*nt + 2*l4;
#pragma unroll
                    for (int r = 0; r < 4; r++) {
                        int qi = (r & 1) ? r1g : r0g;      // rows: 0,2 -> g; wait
                        qi = (r < 2) ? r0g : r1g;
                        int kj = c0 + (r & 1);
                        bool ok = (kj <= qi) && (!use_w || (qi - kj) <= wsv);
                        sacc[nt][r] = ok ? sacc[nt][r]*0.125f : -1e30f;
                    }
                }
            }

            // online softmax: two rows per thread, reduce over quad (l4)
            float mx0 = -1e30f, mx1 = -1e30f;
#pragma unroll
            for (int nt = 0; nt < 8; nt++) {
                mx0 = fmaxf(mx0, fmaxf(sacc[nt][0], sacc[nt][1]));
                mx1 = fmaxf(mx1, fmaxf(sacc[nt][2], sacc[nt][3]));
            }
            mx0 = fmaxf(mx0, __shfl_xor_sync(0xffffffffu, mx0, 1));
            mx0 = fmaxf(mx0, __shfl_xor_sync(0xffffffffu, mx0, 2));
            mx1 = fmaxf(mx1, __shfl_xor_sync(0xffffffffu, mx1, 1));
            mx1 = fmaxf(mx1, __shfl_xor_sync(0xffffffffu, mx1, 2));
            float mn0 = fmaxf(fmaxf(mi0, mx0), -1e29f);
            float mn1 = fmaxf(fmaxf(mi1, mx1), -1e29f);
            float corr0 = __expf(mi0 - mn0);
            float corr1 = __expf(mi1 - mn1);
            float sum0 = 0.f, sum1 = 0.f;
#pragma unroll
            for (int nt = 0; nt < 8; nt++) {
                float p0 = __expf(sacc[nt][0] - mn0);
                float p1 = __expf(sacc[nt][1] - mn0);
                float p2 = __expf(sacc[nt][2] - mn1);
                float p3 = __expf(sacc[nt][3] - mn1);
                sum0 += p0 + p1; sum1 += p2 + p3;
                // write P (tf32) to warp-private rows of QPs
                uint2 w0 = {f2tf32(p0), f2tf32(p1)};
                uint2 w1 = {f2tf32(p2), f2tf32(p3)};
                *(uint2*)(Pw0 + 8*nt + 2*l4) = w0;
                *(uint2*)(Pw1 + 8*nt + 2*l4) = w1;
            }
            sum0 += __shfl_xor_sync(0xffffffffu, sum0, 1);
            sum0 += __shfl_xor_sync(0xffffffffu, sum0, 2);
            sum1 += __shfl_xor_sync(0xffffffffu, sum1, 1);
            sum1 += __shfl_xor_sync(0xffffffffu, sum1, 2);
            li0 = li0*corr0 + sum0;
            li1 = li1*corr1 + sum1;
            mi0 = mn0; mi1 = mn1;
#pragma unroll
            for (int nt = 0; nt < 8; nt++) {
                oacc[nt][0] *= corr0; oacc[nt][1] *= corr0;
                oacc[nt][2] *= corr1; oacc[nt][3] *= corr1;
            }
            __syncwarp();

            // O += P V
#pragma unroll
            for (int ks = 0; ks < 8; ks++) {
                uint32_t a0 = Pw0[8*ks + l4];
                uint32_t a1 = Pw1[8*ks + l4];
                uint32_t a2 = Pw0[8*ks + l4 + 4];
                uint32_t a3 = Pw1[8*ks + l4 + 4];
#pragma unroll
                for (int nt = 0; nt < 8; nt++) {
                    uint32_t b0 = __float_as_uint(Vb[(8*ks + l4)*AST + 8*nt + g]);
                    uint32_t b1 = __float_as_uint(Vb[(8*ks + l4 + 4)*AST + 8*nt + g]);
                    mma_tf32(oacc[nt], a0, a1, a2, a3, b0, b1);
                }
            }
            __syncwarp();
        }
    }

    // epilogue: normalize, gate, write y
    float ga0 = g_ga[(bT + r0g)*HH + h];
    float ga1 = g_ga[(bT + r1g)*HH + h];
    float inv0 = ga0 / li0;
    float inv1 = ga1 / li1;
    float* y0 = g_y + (bT + r0g)*CC + hoff;
    float* y1 = g_y + (bT + r1g)*CC + hoff;
#pragma unroll
    for (int nt = 0; nt < 8; nt++) {
        int c = 8*nt + 2*l4;
        float2 w0 = {oacc[nt][0]*inv0, oacc[nt][1]*inv0};
        float2 w1 = {oacc[nt][2]*inv1, oacc[nt][3]*inv1};
        *(float2*)(y0 + c) = w0;
        *(float2*)(y1 + c) = w1;
    }
}

// ---------------- launch ----------------------------------------------------
extern "C" void kernel_launch(void* const* d_in, const int* in_sizes, int n_in,
                              void* d_out, int out_size) {
    const float* x    = (const float*)d_in[0];
    const float* ve   = (const float*)d_in[1];
    const float* cosb = (const float*)d_in[2];
    const float* sinb = (const float*)d_in[3];
    const float* cqw  = (const float*)d_in[4];
    const float* ckw  = (const float*)d_in[5];
    const float* cvw  = (const float*)d_in[6];
    const float* cpw  = (const float*)d_in[7];
    const float* vgw  = (const float*)d_in[8];
    const float* agw  = (const float*)d_in[9];
    const float* qm   = (const float*)d_in[10];
    const float* km   = (const float*)d_in[11];
    const float* vm   = (const float*)d_in[12];
    const int*   wsp  = (n_in > 13) ? (const int*)d_in[13] : nullptr;
    float* out = (float*)d_out;

    float *pqw, *pkw, *pvw, *pq, *pk, *pv, *py;
    cudaGetSymbolAddress((void**)&pqw, g_qw);
    cudaGetSymbolAddress((void**)&pkw, g_kw);
    cudaGetSymbolAddress((void**)&pvw, g_vw);
    cudaGetSymbolAddress((void**)&pq,  g_q);
    cudaGetSymbolAddress((void**)&pk,  g_k);
    cudaGetSymbolAddress((void**)&pv,  g_v);
    cudaGetSymbolAddress((void**)&py,  g_y);

    // 1) fuse mixes into weights
    fuse_kernel<<<dim3(CC, 3), 256>>>(cqw, ckw, cvw, qm, km, vm);

    // 2) QKV projections (tf32 tensor cores, one launch)
    gemm_tf32_kernel<<<dim3(NROWS/128, CC/128, 3), 256>>>(x, pqw, pq, pkw, pk, pvw, pv, CC);

    // 3) gates + rope + rmsnorm (+ tf32 pre-rounding of q/k/v)
    post_kernel<<<(NROWS*HH*32)/256, 256>>>(x, ve, cosb, sinb, vgw, agw);

    // 4) flash attention (tf32 tensor cores)
    cudaFuncSetAttribute(attn_kernel, cudaFuncAttributeMaxDynamicSharedMemorySize, ATTN_SMEM);
    attn_kernel<<<dim3(TT/128, HH, BB), 256, ATTN_SMEM>>>(wsp);

    // 5) output projection (tf32)
    gemm_tf32_kernel<<<dim3(NROWS/128, CC/128, 1), 256>>>(py, cpw, out, cpw, out, cpw, out, CC);
}

// round 8
// speedup vs baseline: 4.4864x; 1.2717x over previous
#include <cuda_runtime.h>
#include <cstdint>
#include <cstddef>
#include <math.h>

#define BB 2
#define TT 2048
#define CC 1024
#define HH 16
#define NROWS (BB*TT)   // 4096

// ---------------- scratch (static device allocations; no cudaMalloc) -------
__device__ float g_qw[CC*CC];
__device__ float g_kw[CC*CC];
__device__ float g_vw[CC*CC];
__device__ float g_pw[CC*CC];
__device__ float g_xt[NROWS*CC];
__device__ float g_q[NROWS*CC];
__device__ float g_k[NROWS*CC];
__device__ float g_v[NROWS*CC];
__device__ float g_y[NROWS*CC];
__device__ float g_ga[NROWS*HH];

__device__ __forceinline__ void cp_async16(uint32_t saddr, const void* g) {
    asm volatile("cp.async.cg.shared.global [%0], [%1], 16;\n" :: "r"(saddr), "l"(g));
}
__device__ __forceinline__ void cp_commit() {
    asm volatile("cp.async.commit_group;\n");
}
__device__ __forceinline__ void cp_wait0() {
    asm volatile("cp.async.wait_group 0;\n");
}
__device__ __forceinline__ void cp_wait1() {
    asm volatile("cp.async.wait_group 1;\n");
}
__device__ __forceinline__ uint32_t f2tf32(float x) {
    uint32_t r;
    asm("cvt.rna.tf32.f32 %0, %1;" : "=r"(r) : "f"(x));
    return r;
}
__device__ __forceinline__ void mma_tf32(float c[4], uint32_t a0, uint32_t a1,
                                         uint32_t a2, uint32_t a3,
                                         uint32_t b0, uint32_t b1) {
    asm volatile(
        "mma.sync.aligned.m16n8k8.row.col.f32.tf32.tf32.f32 "
        "{%0,%1,%2,%3}, {%4,%5,%6,%7}, {%8,%9}, {%0,%1,%2,%3};"
        : "+f"(c[0]), "+f"(c[1]), "+f"(c[2]), "+f"(c[3])
        : "r"(a0), "r"(a1), "r"(a2), "r"(a3), "r"(b0), "r"(b1));
}

// ---------------- 0) round x to tf32 ----------------------------------------
__global__ void round_x_kernel(const float* __restrict__ x) {
    int i = blockIdx.x * blockDim.x + threadIdx.x;
    float4 v = ((const float4*)x)[i];
    uint4 r = {f2tf32(v.x), f2tf32(v.y), f2tf32(v.z), f2tf32(v.w)};
    ((uint4*)g_xt)[i] = r;
}

// ---------------- 1) fuse mix into weights (tf32-rounded); wi=3 rounds cpw --
__global__ void fuse_kernel(const float* __restrict__ cq, const float* __restrict__ ck,
                            const float* __restrict__ cv, const float* __restrict__ cp,
                            const float* __restrict__ qm,
                            const float* __restrict__ km, const float* __restrict__ vm) {
    int row = blockIdx.x;
    int wi  = blockIdx.y;
    if (wi == 3) {
        for (int c = threadIdx.x; c < CC; c += blockDim.x)
            g_pw[row*CC + c] = __uint_as_float(f2tf32(cp[row*CC + c]));
        return;
    }
    const float* W = (wi == 0) ? cq : (wi == 1) ? ck : cv;
    const float* M = (wi == 0) ? qm : (wi == 1) ? km : vm;
    float* O       = (wi == 0) ? g_qw : (wi == 1) ? g_kw : g_vw;
    int h = row >> 6, d = row & 63;
    float mx[16];
#pragma unroll
    for (int m = 0; m < 16; m++) mx[m] = M[h*16 + m];
    for (int c = threadIdx.x; c < CC; c += blockDim.x) {
        float s = 0.f;
#pragma unroll
        for (int m = 0; m < 16; m++) s += mx[m] * W[(m*64 + d)*CC + c];
        O[row*CC + c] = __uint_as_float(f2tf32(s));
    }
}

// ---------------- 2) NT GEMM, tf32 mma, 3-stage cp.async pipeline -----------
// A and B already tf32-rounded fp32. smem [m][20] (stride 20: conflict-free
// fragments, 80B rows keep 16B cp.async alignment). Block 128x128, BK=16.
#define GST 20
#define GEMM_SMEM (2*3*128*GST*4)   // 61440 B

__global__ __launch_bounds__(256, 2) void gemm_tf32_kernel(
    const float* __restrict__ A,
    const float* __restrict__ B0, float* __restrict__ C0,
    const float* __restrict__ B1, float* __restrict__ C1,
    const float* __restrict__ B2, float* __restrict__ C2,
    int K) {
    const float* Bm = (blockIdx.z == 0) ? B0 : (blockIdx.z == 1) ? B1 : B2;
    float*       Cm = (blockIdx.z == 0) ? C0 : (blockIdx.z == 1) ? C1 : C2;
    const int N = CC;

    extern __shared__ float gsm[];
    float* Asm = gsm;                 // [3][128][20]
    float* Bsm = gsm + 3*128*GST;     // [3][128][20]

    const int tid  = threadIdx.x;
    const int lane = tid & 31;
    const int warp = tid >> 5;
    const int wr = warp & 1;          // 64-row strip
    const int wc = warp >> 1;         // 32-col strip
    const int g  = lane >> 2;
    const int l4 = lane & 3;
    const int brow = blockIdx.x * 128, bcol = blockIdx.y * 128;

    // loader: each thread: row = tid>>1, two 16B chunks c = (tid&1)*2 + {0,1}
    const int lrow = tid >> 1;
    const int lc   = (tid & 1) * 2;
    const float* Ab = A  + (size_t)(brow + lrow) * K + lc*4;
    const float* Bb = Bm + (size_t)(bcol + lrow) * K + lc*4;
    const uint32_t Ad = (uint32_t)__cvta_generic_to_shared(Asm + lrow*GST + lc*4);
    const uint32_t Bd = (uint32_t)__cvta_generic_to_shared(Bsm + lrow*GST + lc*4);
    const uint32_t stageB = 128*GST*4;

    const int NIT = K / 16;   // 64

    // prologue: stages 0,1
#pragma unroll
    for (int s = 0; s < 2; s++) {
        cp_async16(Ad + s*stageB,      Ab + s*16);
        cp_async16(Ad + s*stageB + 16, Ab + s*16 + 4);
        cp_async16(Bd + s*stageB,      Bb + s*16);
        cp_async16(Bd + s*stageB + 16, Bb + s*16 + 4);
        cp_commit();
    }

    float acc[4][4][4];
#pragma unroll
    for (int mi = 0; mi < 4; mi++)
#pragma unroll
        for (int ni = 0; ni < 4; ni++)
#pragma unroll
            for (int r = 0; r < 4; r++) acc[mi][ni][r] = 0.f;

    for (int it = 0; it < NIT; it++) {
        cp_wait1();
        __syncthreads();
        // prefetch stage it+2
        if (it + 2 < NIT) {
            int s = (it + 2) % 3;
            cp_async16(Ad + s*stageB,      Ab + (it+2)*16);
            cp_async16(Ad + s*stageB + 16, Ab + (it+2)*16 + 4);
            cp_async16(Bd + s*stageB,      Bb + (it+2)*16);
            cp_async16(Bd + s*stageB + 16, Bb + (it+2)*16 + 4);
            cp_commit();
        }
        const float* Ap = Asm + (it % 3)*128*GST;
        const float* Bp = Bsm + (it % 3)*128*GST;
#pragma unroll
        for (int ks = 0; ks < 2; ks++) {
            const int k0 = ks*8;
            uint32_t bf[4][2];
#pragma unroll
            for (int ni = 0; ni < 4; ni++) {
                const float* bp = Bp + (wc*32 + ni*8 + g)*GST + k0 + l4;
                bf[ni][0] = __float_as_uint(bp[0]);
                bf[ni][1] = __float_as_uint(bp[4]);
            }
#pragma unroll
            for (int mi = 0; mi < 4; mi++) {
                const float* ap0 = Ap + (wr*64 + mi*16 + g)*GST + k0 + l4;
                const float* ap1 = ap0 + 8*GST;
                uint32_t a0 = __float_as_uint(ap0[0]);
                uint32_t a1 = __float_as_uint(ap1[0]);
                uint32_t a2 = __float_as_uint(ap0[4]);
                uint32_t a3 = __float_as_uint(ap1[4]);
#pragma unroll
                for (int ni = 0; ni < 4; ni++)
                    mma_tf32(acc[mi][ni], a0, a1, a2, a3, bf[ni][0], bf[ni][1]);
            }
        }
    }

#pragma unroll
    for (int mi = 0; mi < 4; mi++) {
#pragma unroll
        for (int ni = 0; ni < 4; ni++) {
            int row0 = brow + wr*64 + mi*16 + g;
            int col  = bcol + wc*32 + ni*8 + 2*l4;
            float2 w0 = {acc[mi][ni][0], acc[mi][ni][1]};
            float2 w1 = {acc[mi][ni][2], acc[mi][ni][3]};
            *(float2*)(Cm + (size_t)row0 * N + col)       = w0;
            *(float2*)(Cm + (size_t)(row0 + 8) * N + col) = w1;
        }
    }
}

// ---------------- 3) gates + RoPE + RMSNorm; q/k/v pre-rounded to tf32 ------
__global__ void post_kernel(const float* __restrict__ x, const float* __restrict__ ve,
                            const float* __restrict__ cosb, const float* __restrict__ sinb,
                            const float* __restrict__ vgw, const float* __restrict__ agw) {
    int gw   = (blockIdx.x * blockDim.x + threadIdx.x) >> 5;
    int lane = threadIdx.x & 31;
    if (gw >= NROWS*HH) return;
    int h  = gw % HH;
    int bt = gw / HH;
    int t  = bt % TT;
    size_t xbase = (size_t)bt * CC;

    float gv = x[xbase + lane] * vgw[h*32 + lane];
#pragma unroll
    for (int o = 16; o > 0; o >>= 1) gv += __shfl_xor_sync(0xffffffffu, gv, o);
    float gate_v = 2.f / (1.f + __expf(-gv));

    float ga = (lane < 12) ? x[xbase + lane] * agw[h*12 + lane] : 0.f;
#pragma unroll
    for (int o = 16; o > 0; o >>= 1) ga += __shfl_xor_sync(0xffffffffu, ga, o);
    if (lane == 0) g_ga[(size_t)bt*HH + h] = 1.f / (1.f + __expf(-ga));

    size_t idx = xbase + h*64;
    float v1 = g_v[idx + lane]      + gate_v * ve[idx + lane];
    float v2 = g_v[idx + lane + 32] + gate_v * ve[idx + lane + 32];
    g_v[idx + lane]      = __uint_as_float(f2tf32(v1));
    g_v[idx + lane + 32] = __uint_as_float(f2tf32(v2));

    float cs = cosb[t*32 + lane], sn = sinb[t*32 + lane];
    {
        float q1 = g_q[idx + lane], q2 = g_q[idx + lane + 32];
        float r1 =  q1*cs + q2*sn;
        float r2 = -q1*sn + q2*cs;
        float ss = r1*r1 + r2*r2;
#pragma unroll
        for (int o = 16; o > 0; o >>= 1) ss += __shfl_xor_sync(0xffffffffu, ss, o);
        float sc = rsqrtf(ss * (1.f/64.f) + 1e-6f);
        g_q[idx + lane]      = __uint_as_float(f2tf32(r1*sc));
        g_q[idx + lane + 32] = __uint_as_float(f2tf32(r2*sc));
    }
    {
        float k1 = g_k[idx + lane], k2 = g_k[idx + lane + 32];
        float r1 =  k1*cs + k2*sn;
        float r2 = -k1*sn + k2*cs;
        float ss = r1*r1 + r2*r2;
#pragma unroll
        for (int o = 16; o > 0; o >>= 1) ss += __shfl_xor_sync(0xffffffffu, ss, o);
        float sc = rsqrtf(ss * (1.f/64.f) + 1e-6f);
        g_k[idx + lane]      = __uint_as_float(f2tf32(r1*sc));
        g_k[idx + lane + 32] = __uint_as_float(f2tf32(r2*sc));
    }
}

// ---------------- 4) flash attention via tf32 mma, BM=128, BN=64 ------------
#define AST 68
#define ATTN_SMEM ((128*AST + 4*64*AST)*4)

__global__ __launch_bounds__(256, 2) void attn_kernel(const int* __restrict__ wsp) {
    extern __shared__ float smf[];
    float* QPs = smf;                       // [128][AST]
    float* Ks  = smf + 128*AST;             // [2][64][AST]
    float* Vs  = Ks  + 2*64*AST;            // [2][64][AST]
    uint32_t* QPu = (uint32_t*)QPs;

    const int qtb = (TT/128 - 1) - blockIdx.x;
    const int h = blockIdx.y, b = blockIdx.z;
    const int tid  = threadIdx.x;
    const int lane = tid & 31;
    const int w    = tid >> 5;
    const int g    = lane >> 2;
    const int l4   = lane & 3;
    const int q0   = qtb * 128;
    const int hoff = h*64;
    const size_t bT = (size_t)b*TT;

    int wsv = wsp ? *wsp : -1;
    const bool use_w = (wsv >= 0) && (wsv < TT - 1);
    int jt0 = 0;
    if (use_w) {
        int lo = q0 - wsv - 63;
        if (lo > 0) jt0 = (lo + 63) >> 6;
    }
    const int jtmax = 2*qtb + 1;

    {
        int row = tid >> 1;
        int c0  = (tid & 1) * 8;
        const float* src = g_q + (bT + q0 + row)*CC + hoff;
        uint32_t dst = (uint32_t)__cvta_generic_to_shared(QPs + row*AST);
#pragma unroll
        for (int i = 0; i < 8; i++) cp_async16(dst + (c0 + i)*16, src + (c0 + i)*4);
        cp_commit();
    }
    {
        int r  = tid >> 2;
        int c0 = (tid & 3) * 4;
        int pos = jt0*64 + r;
        int sh  = (pos > 0) ? pos - 1 : 0;
        uint32_t kd = (uint32_t)__cvta_generic_to_shared(Ks + (jt0&1)*64*AST + r*AST);
        uint32_t vd = (uint32_t)__cvta_generic_to_shared(Vs + (jt0&1)*64*AST + r*AST);
        const float* kp = g_k + (bT + pos)*CC + hoff;
        const float* ks = g_k + (bT + sh)*CC + hoff;
        const float* vp = g_v + (bT + pos)*CC + hoff;
#pragma unroll
        for (int i = 0; i < 4; i++) {
            int c = c0 + i;
            const float* kb = (c < 8) ? kp : ks;
            cp_async16(kd + c*16, kb + c*4);
            cp_async16(vd + c*16, vp + c*4);
        }
        cp_commit();
    }

    uint32_t qa[8][4];
    cp_wait1();
    __syncthreads();
    {
        const float* q0p = QPs + (16*w + g)*AST;
        const float* q1p = QPs + (16*w + g + 8)*AST;
#pragma unroll
        for (int ks = 0; ks < 8; ks++) {
            qa[ks][0] = __float_as_uint(q0p[8*ks + l4]);
            qa[ks][1] = __float_as_uint(q1p[8*ks + l4]);
            qa[ks][2] = __float_as_uint(q0p[8*ks + l4 + 4]);
            qa[ks][3] = __float_as_uint(q1p[8*ks + l4 + 4]);
        }
    }
    __syncwarp();

    float oacc[8][4];
#pragma unroll
    for (int nt = 0; nt < 8; nt++)
#pragma unroll
        for (int r = 0; r < 4; r++) oacc[nt][r] = 0.f;
    float mi0 = -1e30f, mi1 = -1e30f, li0 = 0.f, li1 = 0.f;

    const int wrmin = q0 + 16*w;
    const int wrmax = wrmin + 15;
    const int r0g   = wrmin + g;
    const int r1g   = r0g + 8;
    uint32_t* Pw0 = QPu + (16*w + g)*AST;
    uint32_t* Pw1 = QPu + (16*w + g + 8)*AST;

    for (int jt = jt0; jt <= jtmax; jt++) {
        const int kv0 = jt * 64;
        const int buf = jt & 1;
        cp_wait0();
        __syncthreads();

        if (jt < jtmax) {
            int r  = tid >> 2;
            int c0 = (tid & 3) * 4;
            int pos = kv0 + 64 + r;
            uint32_t kd = (uint32_t)__cvta_generic_to_shared(Ks + (buf^1)*64*AST + r*AST);
            uint32_t vd = (uint32_t)__cvta_generic_to_shared(Vs + (buf^1)*64*AST + r*AST);
            const float* kp = g_k + (bT + pos)*CC + hoff;
            const float* ksh = g_k + (bT + pos - 1)*CC + hoff;
            const float* vp = g_v + (bT + pos)*CC + hoff;
#pragma unroll
            for (int i = 0; i < 4; i++) {
                int c = c0 + i;
                const float* kb = (c < 8) ? kp : ksh;
                cp_async16(kd + c*16, kb + c*4);
                cp_async16(vd + c*16, vp + c*4);
            }
            cp_commit();
        }

        bool dead = (kv0 > wrmax) || (use_w && (kv0 + 63 < wrmin - wsv));
        if (!dead) {
            const float* Kb = Ks + buf*64*AST;
            const float* Vb = Vs + buf*64*AST;

            float sacc[8][4];
#pragma unroll
            for (int nt = 0; nt < 8; nt++)
#pragma unroll
                for (int r = 0; r < 4; r++) sacc[nt][r] = 0.f;
#pragma unroll
            for (int ks = 0; ks < 8; ks++) {
#pragma unroll
                for (int nt = 0; nt < 8; nt++) {
                    uint32_t b0 = __float_as_uint(Kb[(8*nt + g)*AST + 8*ks + l4]);
                    uint32_t b1 = __float_as_uint(Kb[(8*nt + g)*AST + 8*ks + l4 + 4]);
                    mma_tf32(sacc[nt], qa[ks][0], qa[ks][1], qa[ks][2], qa[ks][3], b0, b1);
                }
            }

            const bool full = (kv0 + 63 <= wrmin) &&
                              (!use_w || (wrmax - kv0 <= wsv));
            if (full) {
#pragma unroll
                for (int nt = 0; nt < 8; nt++)
#pragma unroll
                    for (int r = 0; r < 4; r++) sacc[nt][r] *= 0.125f;
            } else {
#pragma unroll
                for (int nt = 0; nt < 8; nt++) {
                    int c0 = kv0 + 8*nt + 2*l4;
#pragma unroll
                    for (int r = 0; r < 4; r++) {
                        int qi = (r < 2) ? r0g : r1g;
                        int kj = c0 + (r & 1);
                        bool ok = (kj <= qi) && (!use_w || (qi - kj) <= wsv);
                        sacc[nt][r] = ok ? sacc[nt][r]*0.125f : -1e30f;
                    }
                }
            }

            float mx0 = -1e30f, mx1 = -1e30f;
#pragma unroll
            for (int nt = 0; nt < 8; nt++) {
                mx0 = fmaxf(mx0, fmaxf(sacc[nt][0], sacc[nt][1]));
                mx1 = fmaxf(mx1, fmaxf(sacc[nt][2], sacc[nt][3]));
            }
            mx0 = fmaxf(mx0, __shfl_xor_sync(0xffffffffu, mx0, 1));
            mx0 = fmaxf(mx0, __shfl_xor_sync(0xffffffffu, mx0, 2));
            mx1 = fmaxf(mx1, __shfl_xor_sync(0xffffffffu, mx1, 1));
            mx1 = fmaxf(mx1, __shfl_xor_sync(0xffffffffu, mx1, 2));
            float mn0 = fmaxf(fmaxf(mi0, mx0), -1e29f);
            float mn1 = fmaxf(fmaxf(mi1, mx1), -1e29f);
            float corr0 = __expf(mi0 - mn0);
            float corr1 = __expf(mi1 - mn1);
            float sum0 = 0.f, sum1 = 0.f;
#pragma unroll
            for (int nt = 0; nt < 8; nt++) {
                float p0 = __expf(sacc[nt][0] - mn0);
                float p1 = __expf(sacc[nt][1] - mn0);
                float p2 = __expf(sacc[nt][2] - mn1);
                float p3 = __expf(sacc[nt][3] - mn1);
                sum0 += p0 + p1; sum1 += p2 + p3;
                uint2 w0 = {f2tf32(p0), f2tf32(p1)};
                uint2 w1 = {f2tf32(p2), f2tf32(p3)};
                *(uint2*)(Pw0 + 8*nt + 2*l4) = w0;
                *(uint2*)(Pw1 + 8*nt + 2*l4) = w1;
            }
            sum0 += __shfl_xor_sync(0xffffffffu, sum0, 1);
            sum0 += __shfl_xor_sync(0xffffffffu, sum0, 2);
            sum1 += __shfl_xor_sync(0xffffffffu, sum1, 1);
            sum1 += __shfl_xor_sync(0xffffffffu, sum1, 2);
            li0 = li0*corr0 + sum0;
            li1 = li1*corr1 + sum1;
            mi0 = mn0; mi1 = mn1;
#pragma unroll
            for (int nt = 0; nt < 8; nt++) {
                oacc[nt][0] *= corr0; oacc[nt][1] *= corr0;
                oacc[nt][2] *= corr1; oacc[nt][3] *= corr1;
            }
            __syncwarp();

#pragma unroll
            for (int ks = 0; ks < 8; ks++) {
                uint32_t a0 = Pw0[8*ks + l4];
                uint32_t a1 = Pw1[8*ks + l4];
                uint32_t a2 = Pw0[8*ks + l4 + 4];
                uint32_t a3 = Pw1[8*ks + l4 + 4];
#pragma unroll
                for (int nt = 0; nt < 8; nt++) {
                    uint32_t b0 = __float_as_uint(Vb[(8*ks + l4)*AST + 8*nt + g]);
                    uint32_t b1 = __float_as_uint(Vb[(8*ks + l4 + 4)*AST + 8*nt + g]);
                    mma_tf32(oacc[nt], a0, a1, a2, a3, b0, b1);
                }
            }
            __syncwarp();
        }
    }

    // epilogue: normalize, gate, write y (tf32-rounded for the proj GEMM)
    float ga0 = g_ga[(bT + r0g)*HH + h];
    float ga1 = g_ga[(bT + r1g)*HH + h];
    float inv0 = ga0 / li0;
    float inv1 = ga1 / li1;
    float* y0 = g_y + (bT + r0g)*CC + hoff;
    float* y1 = g_y + (bT + r1g)*CC + hoff;
#pragma unroll
    for (int nt = 0; nt < 8; nt++) {
        int c = 8*nt + 2*l4;
        uint2 w0 = {f2tf32(oacc[nt][0]*inv0), f2tf32(oacc[nt][1]*inv0)};
        uint2 w1 = {f2tf32(oacc[nt][2]*inv1), f2tf32(oacc[nt][3]*inv1)};
        *(uint2*)(y0 + c) = w0;
        *(uint2*)(y1 + c) = w1;
    }
}

// ---------------- launch ----------------------------------------------------
extern "C" void kernel_launch(void* const* d_in, const int* in_sizes, int n_in,
                              void* d_out, int out_size) {
    const float* x    = (const float*)d_in[0];
    const float* ve   = (const float*)d_in[1];
    const float* cosb = (const float*)d_in[2];
    const float* sinb = (const float*)d_in[3];
    const float* cqw  = (const float*)d_in[4];
    const float* ckw  = (const float*)d_in[5];
    const float* cvw  = (const float*)d_in[6];
    const float* cpw  = (const float*)d_in[7];
    const float* vgw  = (const float*)d_in[8];
    const float* agw  = (const float*)d_in[9];
    const float* qm   = (const float*)d_in[10];
    const float* km   = (const float*)d_in[11];
    const float* vm   = (const float*)d_in[12];
    const int*   wsp  = (n_in > 13) ? (const int*)d_in[13] : nullptr;
    float* out = (float*)d_out;

    float *pqw, *pkw, *pvw, *ppw, *pxt, *pq, *pk, *pv, *py;
    cudaGetSymbolAddress((void**)&pqw, g_qw);
    cudaGetSymbolAddress((void**)&pkw, g_kw);
    cudaGetSymbolAddress((void**)&pvw, g_vw);
    cudaGetSymbolAddress((void**)&ppw, g_pw);
    cudaGetSymbolAddress((void**)&pxt, g_xt);
    cudaGetSymbolAddress((void**)&pq,  g_q);
    cudaGetSymbolAddress((void**)&pk,  g_k);
    cudaGetSymbolAddress((void**)&pv,  g_v);
    cudaGetSymbolAddress((void**)&py,  g_y);

    // 0) round x to tf32
    round_x_kernel<<<NROWS*CC/1024, 256>>>(x);

    // 1) fuse mixes into weights (rounded) + round cpw
    fuse_kernel<<<dim3(CC, 4), 256>>>(cqw, ckw, cvw, cpw, qm, km, vm);

    // 2) QKV projections
    cudaFuncSetAttribute(gemm_tf32_kernel, cudaFuncAttributeMaxDynamicSharedMemorySize, GEMM_SMEM);
    gemm_tf32_kernel<<<dim3(NROWS/128, CC/128, 3), 256, GEMM_SMEM>>>(
        pxt, pqw, pq, pkw, pk, pvw, pv, CC);

    // 3) gates + rope + rmsnorm (+ tf32 rounding)
    post_kernel<<<(NROWS*HH*32)/256, 256>>>(x, ve, cosb, sinb, vgw, agw);

    // 4) flash attention (tf32 tensor cores)
    cudaFuncSetAttribute(attn_kernel, cudaFuncAttributeMaxDynamicSharedMemorySize, ATTN_SMEM);
    attn_kernel<<<dim3(TT/128, HH, BB), 256, ATTN_SMEM>>>(wsp);

    // 5) output projection
    gemm_tf32_kernel<<<dim3(NROWS/128, CC/128, 1), 256, GEMM_SMEM>>>(
        py, ppw, out, ppw, out, ppw, out, CC);
}